// round 8
// baseline (speedup 1.0000x reference)
#include <cuda_runtime.h>
#include <math.h>

// ---------------------------------------------------------------------------
// PlaneElement fused, R8: MLP-4 staging, pure-log Manning flux, |.|-identity
// infiltration sum, float2 LDS window. Monotone-vel finale (1 manning/elem).
// EPT=14/TILE=3584 -> 1171 blocks = one wave at 8 blocks/SM.
// Output: [outflow_q, infil_rate_element, infil_depth_element, max_cfl]
// ---------------------------------------------------------------------------

#define BLOCK 256
#define EPT   14
#define TILE  (BLOCK * EPT)      // 3584
#define MAX_BLOCKS 8192
#define EPSF  1e-8f

struct CC {
    float cA1, cA0;    // A = max(cA1*d + cA0, 0)
    float kt1, kt0;    // t = kt1*d + kt0 ; infil = cSd*d + cN - 0.5*|t| (summed)
    float cSd, cN;     // 0.5*(Kb+1), 0.5*(Ka+raindt)
    float csw, WID;    // wp = csw*A + WID
    float l2cman;      // log2(sqrt(SL)/MAN)
    float dtdx, inv_dt;
    float pad;
};

__constant__ CC g_cc;
__device__  CC g_dc;
__device__ float        g_psd [MAX_BLOCKS];   // per-block sum d
__device__ float        g_pst [MAX_BLOCKS];   // per-block sum |t|
__device__ float        g_pmax[MAX_BLOCKS];   // per-block max A_next
__device__ float        g_outflow;
__device__ unsigned int g_count = 0;

__device__ __forceinline__ float fast_lg2(float x)
{ float r; asm("lg2.approx.f32 %0, %1;" : "=f"(r) : "f"(x)); return r; }
__device__ __forceinline__ float fast_ex2(float x)
{ float r; asm("ex2.approx.f32 %0, %1;" : "=f"(r) : "f"(x)); return r; }

// ---------------------------------------------------------------------------
__global__ void setup_kernel(const float* rain_rate, const float* dt,
                             const float* theta_current, const float* F_cumulative,
                             const float* WID, const float* SS1, const float* SS2,
                             const float* MAN, const float* SL, const float* dx,
                             const float* Ks, const float* psi, const float* theta_s)
{
    __shared__ float v[13];
    const float* ptrs[13] = { rain_rate, dt, theta_current, F_cumulative, WID,
                              SS1, SS2, MAN, SL, dx, Ks, psi, theta_s };
    int t = threadIdx.x;
    if (t < 13) v[t] = __ldg(ptrs[t]);
    __syncthreads();
    if (t == 0) {
        float rr = v[0], dtv = v[1], th = v[2], F = v[3], wid = v[4];
        float ss1 = v[5], ss2 = v[6], man = v[7], sl = v[8], dxv = v[9];
        float ks = v[10], ps = v[11], ths = v[12];
        CC c;
        float dtheta = fmaxf(ths - th, 0.0f);
        float F_safe = fmaxf(F, 1e-6f);
        float ksdt   = ks * dtv;
        float Kb     = ksdt / F_safe;
        float Ka     = ksdt + Kb * (ps * dtheta);
        float raindt = rr * dtv;
        c.cA1    = (1.0f - Kb) * wid;
        c.cA0    = (raindt - Ka) * wid;
        c.kt1    = Kb - 1.0f;
        c.kt0    = Ka - raindt;
        c.cSd    = 0.5f * (Kb + 1.0f);
        c.cN     = 0.5f * (Ka + raindt);
        c.WID    = wid;
        c.csw    = (sqrtf(1.0f + ss1 * ss1) + sqrtf(1.0f + ss2 * ss2)) / wid;
        c.l2cman = log2f(sqrtf(sl) / man);
        c.dtdx   = dtv / dxv;
        c.inv_dt = 1.0f / dtv;
        c.pad    = 0.0f;
        g_dc = c;
    }
}

// full manning p' = (max(A,EPS)/wp)^(2/3)*cman  (finale / edge / outflow path)
__device__ __forceinline__ float manning_pc(float A)
{
    float wp = fmaf(g_cc.csw, A, g_cc.WID);
    float As = fmaxf(A, EPSF);
    float r  = __fdividef(As, wp);
    return fast_ex2(fmaf(0.66666667f, fast_lg2(r), g_cc.l2cman));
}

__device__ __forceinline__ float ga_Afast(float d)
{ return fmaxf(fmaf(g_cc.cA1, d, g_cc.cA0), 0.0f); }

// pure-log minmod flux: Af >= 0 always; flux(0) = 0 via lg2(0) = -inf
__device__ __forceinline__ float flux_log(float a, float b, float A0)
{
    float m  = (fabsf(a) < fabsf(b)) ? a : b;
    float s  = (a * b > 0.0f) ? m : 0.0f;
    float Af = fmaf(0.5f, s, A0);
    float wp = fmaf(g_cc.csw, Af, g_cc.WID);
    float e  = fmaf(1.66666667f, fast_lg2(Af),
               fmaf(-0.66666667f, fast_lg2(wp), g_cc.l2cman));
    return fast_ex2(e);
}

// staging: d4 -> A4 into smem; accumulate sum(d), sum(|t|)
__device__ __forceinline__ float4 stage4(float4 d, float& sd, float& st)
{
    sd += (d.x + d.y) + (d.z + d.w);
    st += fabsf(fmaf(g_cc.kt1, d.x, g_cc.kt0));
    st += fabsf(fmaf(g_cc.kt1, d.y, g_cc.kt0));
    st += fabsf(fmaf(g_cc.kt1, d.z, g_cc.kt0));
    st += fabsf(fmaf(g_cc.kt1, d.w, g_cc.kt0));
    float4 a;
    a.x = ga_Afast(d.x); a.y = ga_Afast(d.y);
    a.z = ga_Afast(d.z); a.w = ga_Afast(d.w);
    return a;
}

__global__ void __launch_bounds__(BLOCK, 8)
fused_kernel(const float* __restrict__ depth, int N, int nblocks,
             float* __restrict__ out)
{
    __shared__ __align__(16) float sAraw[TILE + 8];
    __shared__ float w0[BLOCK / 32], w1[BLOCK / 32], w2[BLOCK / 32];
    __shared__ int   s_last;

    const int tid  = threadIdx.x;
    const int base = blockIdx.x * TILE;
    const bool interior = (base >= 2) && (base + TILE + 2 <= N);

    float sum_d = 0.0f, sum_t = 0.0f;
    float maxA  = 0.0f;

    if (interior) {
        // ---- staging: all LDGs issued up front (MLP=4) ----
        const float4* dp = (const float4*)(depth + base);
        const bool has3 = tid < (TILE / 4 - 3 * BLOCK);   // 128 threads
        float4 d0 = __ldg(dp + tid);
        float4 d1 = __ldg(dp + tid + BLOCK);
        float4 d2 = __ldg(dp + tid + 2 * BLOCK);
        float4 d3;
        if (has3) d3 = __ldg(dp + tid + 3 * BLOCK);
        float dh = 0.0f; int hk = 0;
        if (tid < 3) {
            int g = (tid < 2) ? (base - 2 + tid) : (base + TILE);
            hk = g - base + 4;
            dh = __ldg(depth + g);
        }

        float4* sA4 = (float4*)(sAraw + 4);
        sA4[tid]             = stage4(d0, sum_d, sum_t);
        sA4[tid + BLOCK]     = stage4(d1, sum_d, sum_t);
        sA4[tid + 2 * BLOCK] = stage4(d2, sum_d, sum_t);
        if (has3) sA4[tid + 3 * BLOCK] = stage4(d3, sum_d, sum_t);
        if (tid < 3) sAraw[hk] = ga_Afast(dh);     // halo (not owned: no sums)
        __syncthreads();

        // ---- float2 rolling window: 15 fluxes, 14 updates ----
        const float2* sA2 = (const float2*)sAraw;
        const int h = 7 * tid + 1;                 // (14*tid + 2) / 2
        float2 p = sA2[h];                         // A[-2], A[-1]
        float2 q = sA2[h + 1];                     // A[0],  A[1]
        float a = p.y - p.x;
        float b = q.x - p.y;
        float flux_prev = flux_log(a, b, p.y);     // node t0-1
        float Acur = q.x, Anxt = q.y;
        a = b;
        b = Anxt - Acur;
        #pragma unroll
        for (int k = 0; k < EPT / 2; k++) {
            float2 r = sA2[h + 2 + k];             // A[2k+2], A[2k+3]
            float f0  = flux_log(a, b, Acur);
            float An0 = fmaxf(fmaf(-g_cc.dtdx, f0 - flux_prev, Acur), 0.0f);
            float a1 = b, b1 = r.x - Anxt;
            float f1  = flux_log(a1, b1, Anxt);
            float An1 = fmaxf(fmaf(-g_cc.dtdx, f1 - f0, Anxt), 0.0f);
            maxA = fmaxf(maxA, fmaxf(An0, An1));
            flux_prev = f1;
            a = b1;
            b = r.y - r.x;
            Acur = r.x; Anxt = r.y;
        }
    } else {
        // ---- edge blocks (2): guarded staging + guarded window ----
        #pragma unroll 1
        for (int k = tid; k < TILE + 3; k += BLOCK) {
            int g = base - 2 + k;
            float Aval = 0.0f;
            if (g >= 0 && g < N) {
                float d = depth[g];
                Aval = ga_Afast(d);
                if (g >= base) {
                    sum_d += d;
                    sum_t += fabsf(fmaf(g_cc.kt1, d, g_cc.kt0));
                }
            }
            sAraw[k + 2] = Aval;
        }
        __syncthreads();

        const int t0 = base + tid * EPT;
        float flux_prev = 0.0f;
        {
            int j = t0 - 1;
            if (j >= 0 && j < N) {
                int sj = j - base + 4;
                float A = sAraw[sj];
                float slope = 0.0f;
                if (j > 0 && j < N - 1) {
                    float a = A - sAraw[sj - 1];
                    float b = sAraw[sj + 1] - A;
                    float m = (fabsf(a) < fabsf(b)) ? a : b;
                    slope   = (a * b > 0.0f) ? m : 0.0f;
                }
                float Af = fmaf(0.5f, slope, A);
                flux_prev = Af * manning_pc(Af);
            }
        }
        #pragma unroll 1
        for (int i = 0; i < EPT; i++) {
            int g = t0 + i;
            if (g >= N) break;
            int sg = g - base + 4;
            float A = sAraw[sg];
            float slope = 0.0f;
            if (g > 0 && g < N - 1) {
                float a = A - sAraw[sg - 1];
                float b = sAraw[sg + 1] - A;
                float m = (fabsf(a) < fabsf(b)) ? a : b;
                slope   = (a * b > 0.0f) ? m : 0.0f;
            }
            float Af    = fmaf(0.5f, slope, A);
            float fluxj = Af * manning_pc(Af);
            float flux_in = (g == 0) ? 0.0f : flux_prev;
            float A_next  = fmaxf(fmaf(-g_cc.dtdx, fluxj - flux_in, A), 0.0f);
            maxA = fmaxf(maxA, A_next);
            if (g == N - 1) g_outflow = A_next * manning_pc(A_next);
            flux_prev = fluxj;
        }
    }

    // ---- deterministic block reduction: sum_d, sum_t, maxA ----
    #pragma unroll
    for (int o = 16; o > 0; o >>= 1) {
        sum_d += __shfl_down_sync(0xffffffffu, sum_d, o);
        sum_t += __shfl_down_sync(0xffffffffu, sum_t, o);
        maxA   = fmaxf(maxA, __shfl_down_sync(0xffffffffu, maxA, o));
    }
    int warp = tid >> 5, lane = tid & 31;
    if (lane == 0) { w0[warp] = sum_d; w1[warp] = sum_t; w2[warp] = maxA; }
    __syncthreads();
    if (tid == 0) {
        float sd = 0.0f, st = 0.0f, m = 0.0f;
        #pragma unroll
        for (int w = 0; w < BLOCK / 32; w++) {
            sd += w0[w];
            st += w1[w];
            m   = fmaxf(m, w2[w]);
        }
        g_psd[blockIdx.x]  = sd;
        g_pst[blockIdx.x]  = st;
        g_pmax[blockIdx.x] = m;
        __threadfence();
        unsigned int ticket = atomicAdd(&g_count, 1u);
        s_last = (ticket == (unsigned int)(nblocks - 1)) ? 1 : 0;
    }
    __syncthreads();

    // ---- last block: fixed-order grid reduction + outputs ----
    if (s_last) {
        __threadfence();
        float sd = 0.0f, st = 0.0f, m = 0.0f;
        for (int i = tid; i < nblocks; i += BLOCK) {
            sd += g_psd[i];
            st += g_pst[i];
            m   = fmaxf(m, g_pmax[i]);
        }
        #pragma unroll
        for (int o = 16; o > 0; o >>= 1) {
            sd += __shfl_down_sync(0xffffffffu, sd, o);
            st += __shfl_down_sync(0xffffffffu, st, o);
            m   = fmaxf(m, __shfl_down_sync(0xffffffffu, m, o));
        }
        if (lane == 0) { w0[warp] = sd; w1[warp] = st; w2[warp] = m; }
        __syncthreads();
        if (tid == 0) {
            float tsd = 0.0f, tst = 0.0f, mA = 0.0f;
            #pragma unroll
            for (int w = 0; w < BLOCK / 32; w++) {
                tsd += w0[w];
                tst += w1[w];
                mA   = fmaxf(mA, w2[w]);
            }
            // sum infil = cSd*sum(d) + cN*N - 0.5*sum|t|
            float sinfil = fmaf(g_cc.cSd, tsd,
                           fmaf(-0.5f, tst, g_cc.cN * (float)N));
            float mean_depth = sinfil / (float)N;
            // vel monotone in A_next -> single evaluation at the max
            float vel = manning_pc(mA) * fminf(mA * 1e8f, 1.0f);
            out[0] = g_outflow;
            out[1] = mean_depth * g_cc.inv_dt;
            out[2] = mean_depth;
            out[3] = vel * g_cc.dtdx;
            g_count = 0;   // reset for next graph replay
        }
    }
}

// ---------------------------------------------------------------------------
extern "C" void kernel_launch(void* const* d_in, const int* in_sizes, int n_in,
                              void* d_out, int out_size)
{
    const float* depth = (const float*)d_in[0];
    const int N = in_sizes[0];
    int nblocks = (N + TILE - 1) / TILE;   // N=2^22 -> 1171 blocks (one wave)
    if (nblocks > MAX_BLOCKS) nblocks = MAX_BLOCKS;

    setup_kernel<<<1, 32>>>(
        (const float*)d_in[1],  (const float*)d_in[2],  (const float*)d_in[4],
        (const float*)d_in[5],  (const float*)d_in[6],  (const float*)d_in[7],
        (const float*)d_in[8],  (const float*)d_in[9],  (const float*)d_in[10],
        (const float*)d_in[11], (const float*)d_in[12], (const float*)d_in[13],
        (const float*)d_in[14]);

    void* src = nullptr;
    cudaGetSymbolAddress(&src, g_dc);
    cudaMemcpyToSymbolAsync(g_cc, src, sizeof(CC), 0, cudaMemcpyDeviceToDevice);

    fused_kernel<<<nblocks, BLOCK>>>(depth, N, nblocks, (float*)d_out);
}

// round 9
// speedup vs baseline: 1.0034x; 1.0034x over previous
#include <cuda_runtime.h>
#include <math.h>

// ---------------------------------------------------------------------------
// PlaneElement fused, R9: SINGLE kernel launch. Per-block constants (warp 0
// parallel-loads 13 scalars, thread 0 derives, smem broadcast). R7 interior
// math (best measured): smem-staged A, rolling flux window, monotone-vel
// reduction (max A_next only). BLOCK=512/EPT=14 -> 586 blocks ~ one wave.
// Output: [outflow_q, infil_rate_element, infil_depth_element, max_cfl]
// ---------------------------------------------------------------------------

#define BLOCK 512
#define EPT   14
#define TILE  (BLOCK * EPT)      // 7168
#define MAX_BLOCKS 8192
#define EPSF  1e-8f

struct CC {
    float cA1, cA0;    // A = max(cA1*d + cA0, 0)
    float Ka, Kb;      // fp*dt = Ka + Kb*d
    float raindt;      // avail = raindt + d
    float csw, WID;    // wp = csw*A + WID
    float l2cman;      // log2(sqrt(SL)/MAN)
    float dtdx, inv_dt;
};

__device__ float        g_psum[MAX_BLOCKS];
__device__ float        g_pmax[MAX_BLOCKS];   // per-block max A_next
__device__ float        g_outflow;
__device__ unsigned int g_count = 0;

__device__ __forceinline__ float fast_lg2(float x)
{ float r; asm("lg2.approx.f32 %0, %1;" : "=f"(r) : "f"(x)); return r; }
__device__ __forceinline__ float fast_ex2(float x)
{ float r; asm("ex2.approx.f32 %0, %1;" : "=f"(r) : "f"(x)); return r; }

// p' = (max(A,EPS)/wp)^(2/3) * cman ; manning q = A * p'
__device__ __forceinline__ float manning_pc(float A, float csw, float WID, float l2cman)
{
    float wp = fmaf(csw, A, WID);
    float As = fmaxf(A, EPSF);
    float r  = __fdividef(As, wp);
    return fast_ex2(fmaf(0.66666667f, fast_lg2(r), l2cman));
}

// minmod flux with diffs: a = A0 - A_left, b = A_right - A0
__device__ __forceinline__ float flux_mm(float a, float b, float A0,
                                         float csw, float WID, float l2cman)
{
    float m  = (fabsf(a) < fabsf(b)) ? a : b;
    float s  = (a * b > 0.0f) ? m : 0.0f;
    float Af = fmaf(0.5f, s, A0);
    return Af * manning_pc(Af, csw, WID, l2cman);
}

__global__ void __launch_bounds__(BLOCK, 4)
fused_kernel(const float* __restrict__ depth, int N, int nblocks,
             float* __restrict__ out,
             const float* rain_rate, const float* dt,
             const float* theta_current, const float* F_cumulative,
             const float* WID_p, const float* SS1, const float* SS2,
             const float* MAN, const float* SL, const float* dx,
             const float* Ks, const float* psi, const float* theta_s)
{
    __shared__ __align__(16) float sAraw[TILE + 8];
    __shared__ float sv[13];
    __shared__ CC    sc;
    __shared__ float w0[BLOCK / 32], w1[BLOCK / 32];
    __shared__ int   s_last;

    const int tid  = threadIdx.x;
    const int base = blockIdx.x * TILE;

    // ---- per-block constants: warp 0 loads 13 scalars in parallel ----
    if (tid < 32) {
        if      (tid == 0)  sv[0]  = __ldg(rain_rate);
        else if (tid == 1)  sv[1]  = __ldg(dt);
        else if (tid == 2)  sv[2]  = __ldg(theta_current);
        else if (tid == 3)  sv[3]  = __ldg(F_cumulative);
        else if (tid == 4)  sv[4]  = __ldg(WID_p);
        else if (tid == 5)  sv[5]  = __ldg(SS1);
        else if (tid == 6)  sv[6]  = __ldg(SS2);
        else if (tid == 7)  sv[7]  = __ldg(MAN);
        else if (tid == 8)  sv[8]  = __ldg(SL);
        else if (tid == 9)  sv[9]  = __ldg(dx);
        else if (tid == 10) sv[10] = __ldg(Ks);
        else if (tid == 11) sv[11] = __ldg(psi);
        else if (tid == 12) sv[12] = __ldg(theta_s);
        __syncwarp();
        if (tid == 0) {
            float rr = sv[0], dtv = sv[1], th = sv[2], F = sv[3], wid = sv[4];
            float ss1 = sv[5], ss2 = sv[6], man = sv[7], sl = sv[8], dxv = sv[9];
            float ks = sv[10], ps = sv[11], ths = sv[12];
            float dtheta = fmaxf(ths - th, 0.0f);
            float F_safe = fmaxf(F, 1e-6f);
            float ksdt   = ks * dtv;
            float Kb     = ksdt / F_safe;
            float Ka     = ksdt + Kb * (ps * dtheta);
            float raindt = rr * dtv;
            sc.Kb     = Kb;
            sc.Ka     = Ka;
            sc.raindt = raindt;
            sc.cA1    = (1.0f - Kb) * wid;
            sc.cA0    = (raindt - Ka) * wid;
            sc.WID    = wid;
            sc.csw    = (sqrtf(1.0f + ss1 * ss1) + sqrtf(1.0f + ss2 * ss2)) / wid;
            sc.l2cman = log2f(sqrtf(sl) / man);
            sc.dtdx   = dtv / dxv;
            sc.inv_dt = 1.0f / dtv;
        }
    }
    __syncthreads();

    const float cA1 = sc.cA1, cA0 = sc.cA0;
    const float Kb = sc.Kb, Ka = sc.Ka, raindt = sc.raindt;
    const float csw = sc.csw, WID = sc.WID, l2cman = sc.l2cman;
    const float dtdx = sc.dtdx;

    const bool interior = (base >= 2) && (base + TILE + 2 <= N);

    float local_sum  = 0.0f;
    float local_maxA = 0.0f;

    if (interior) {
        // ---- stage A into smem (coalesced float4), accumulate infil ----
        const float4* dp = (const float4*)(depth + base);
        float4* sA4 = (float4*)(sAraw + 4);
        #pragma unroll 1
        for (int idx = tid; idx < TILE / 4; idx += BLOCK) {
            float4 d4 = __ldg(dp + idx);
            float4 a4;
            a4.x = fmaxf(fmaf(cA1, d4.x, cA0), 0.0f);
            a4.y = fmaxf(fmaf(cA1, d4.y, cA0), 0.0f);
            a4.z = fmaxf(fmaf(cA1, d4.z, cA0), 0.0f);
            a4.w = fmaxf(fmaf(cA1, d4.w, cA0), 0.0f);
            local_sum += (fminf(fmaf(Kb, d4.x, Ka), raindt + d4.x)
                        + fminf(fmaf(Kb, d4.y, Ka), raindt + d4.y))
                       + (fminf(fmaf(Kb, d4.z, Ka), raindt + d4.z)
                        + fminf(fmaf(Kb, d4.w, Ka), raindt + d4.w));
            sA4[idx] = a4;
        }
        if (tid < 3) {
            int g = (tid < 2) ? (base - 2 + tid) : (base + TILE);
            sAraw[g - base + 4] = fmaxf(fmaf(cA1, __ldg(depth + g), cA0), 0.0f);
        }
        __syncthreads();

        // ---- rolling window, carried diff; reduce max A_next only ----
        const int s0 = tid * EPT + 2;          // sAraw[s0] = A(t0-2)
        float Acur = sAraw[s0 + 1];
        float Anxt = sAraw[s0 + 2];
        float a = Acur - sAraw[s0];
        float b = Anxt - Acur;
        float flux_prev = flux_mm(a, b, Acur, csw, WID, l2cman);   // node t0-1
        #pragma unroll
        for (int i = 0; i < EPT; i++) {
            Acur = Anxt;
            Anxt = sAraw[s0 + 3 + i];
            a = b;
            b = Anxt - Acur;
            float fluxj  = flux_mm(a, b, Acur, csw, WID, l2cman);
            float A_next = fmaxf(fmaf(-dtdx, fluxj - flux_prev, Acur), 0.0f);
            local_maxA   = fmaxf(local_maxA, A_next);
            flux_prev    = fluxj;
        }
    } else {
        // ---- edge blocks (2): guarded staging + guarded window ----
        #pragma unroll 1
        for (int k = tid; k < TILE + 3; k += BLOCK) {
            int g = base - 2 + k;
            float Aval = 0.0f;
            if (g >= 0 && g < N) {
                float d = depth[g];
                Aval = fmaxf(fmaf(cA1, d, cA0), 0.0f);
                if (g >= base) local_sum += fminf(fmaf(Kb, d, Ka), raindt + d);
            }
            sAraw[k + 2] = Aval;
        }
        __syncthreads();

        const int t0 = base + tid * EPT;
        float flux_prev = 0.0f;
        {
            int j = t0 - 1;
            if (j >= 0 && j < N) {
                int sj = j - base + 4;
                float A = sAraw[sj];
                float slope = 0.0f;
                if (j > 0 && j < N - 1) {
                    float a = A - sAraw[sj - 1];
                    float b = sAraw[sj + 1] - A;
                    float m = (fabsf(a) < fabsf(b)) ? a : b;
                    slope   = (a * b > 0.0f) ? m : 0.0f;
                }
                float Af = fmaf(0.5f, slope, A);
                flux_prev = Af * manning_pc(Af, csw, WID, l2cman);
            }
        }
        #pragma unroll 1
        for (int i = 0; i < EPT; i++) {
            int g = t0 + i;
            if (g >= N) break;
            int sg = g - base + 4;
            float A = sAraw[sg];
            float slope = 0.0f;
            if (g > 0 && g < N - 1) {
                float a = A - sAraw[sg - 1];
                float b = sAraw[sg + 1] - A;
                float m = (fabsf(a) < fabsf(b)) ? a : b;
                slope   = (a * b > 0.0f) ? m : 0.0f;
            }
            float Af    = fmaf(0.5f, slope, A);
            float fluxj = Af * manning_pc(Af, csw, WID, l2cman);
            float flux_in = (g == 0) ? 0.0f : flux_prev;
            float A_next  = fmaxf(fmaf(-dtdx, fluxj - flux_in, A), 0.0f);
            local_maxA    = fmaxf(local_maxA, A_next);
            if (g == N - 1)
                g_outflow = A_next * manning_pc(A_next, csw, WID, l2cman);
            flux_prev = fluxj;
        }
    }

    // ---- deterministic block reduction (sum infil, max A_next) ----
    #pragma unroll
    for (int o = 16; o > 0; o >>= 1) {
        local_sum  += __shfl_down_sync(0xffffffffu, local_sum, o);
        local_maxA  = fmaxf(local_maxA, __shfl_down_sync(0xffffffffu, local_maxA, o));
    }
    int warp = tid >> 5, lane = tid & 31;
    if (lane == 0) { w0[warp] = local_sum; w1[warp] = local_maxA; }
    __syncthreads();
    if (tid == 0) {
        float s = 0.0f, m = 0.0f;
        #pragma unroll
        for (int w = 0; w < BLOCK / 32; w++) {
            s += w0[w];
            m  = fmaxf(m, w1[w]);
        }
        g_psum[blockIdx.x] = s;
        g_pmax[blockIdx.x] = m;
        __threadfence();
        unsigned int ticket = atomicAdd(&g_count, 1u);
        s_last = (ticket == (unsigned int)(nblocks - 1)) ? 1 : 0;
    }
    __syncthreads();

    // ---- last block: fixed-order grid reduction, single vel eval ----
    if (s_last) {
        __threadfence();
        float s = 0.0f, m = 0.0f;
        for (int i = tid; i < nblocks; i += BLOCK) {
            s += g_psum[i];
            m  = fmaxf(m, g_pmax[i]);
        }
        #pragma unroll
        for (int o = 16; o > 0; o >>= 1) {
            s += __shfl_down_sync(0xffffffffu, s, o);
            m  = fmaxf(m, __shfl_down_sync(0xffffffffu, m, o));
        }
        if (lane == 0) { w0[warp] = s; w1[warp] = m; }
        __syncthreads();
        if (tid == 0) {
            float st = 0.0f, mA = 0.0f;
            #pragma unroll
            for (int w = 0; w < BLOCK / 32; w++) {
                st += w0[w];
                mA  = fmaxf(mA, w1[w]);
            }
            // vel(A) = p(A) * min(A*1e8, 1) is monotone in A -> one evaluation
            float vel = manning_pc(mA, csw, WID, l2cman) * fminf(mA * 1e8f, 1.0f);
            float mean_depth = st / (float)N;
            out[0] = g_outflow;
            out[1] = mean_depth * sc.inv_dt;
            out[2] = mean_depth;
            out[3] = vel * dtdx;
            g_count = 0;   // reset for next graph replay
        }
    }
}

// ---------------------------------------------------------------------------
extern "C" void kernel_launch(void* const* d_in, const int* in_sizes, int n_in,
                              void* d_out, int out_size)
{
    const float* depth = (const float*)d_in[0];
    const int N = in_sizes[0];
    int nblocks = (N + TILE - 1) / TILE;   // N=2^22 -> 586 blocks (~one wave)
    if (nblocks > MAX_BLOCKS) nblocks = MAX_BLOCKS;

    fused_kernel<<<nblocks, BLOCK>>>(
        depth, N, nblocks, (float*)d_out,
        (const float*)d_in[1],  (const float*)d_in[2],  (const float*)d_in[4],
        (const float*)d_in[5],  (const float*)d_in[6],  (const float*)d_in[7],
        (const float*)d_in[8],  (const float*)d_in[9],  (const float*)d_in[10],
        (const float*)d_in[11], (const float*)d_in[12], (const float*)d_in[13],
        (const float*)d_in[14]);
}